// round 15
// baseline (speedup 1.0000x reference)
#include <cuda_runtime.h>
#include <cuda_fp16.h>
#include <math.h>
#include <stdint.h>

// GRU: inputs[64,512,1024], h0[1,64,1024], weight_ih[3072,1024], weight_hh[3072,1024],
//      bias_ih[3072], bias_hh[3072]
// out = concat(outputs[64,512,1024], hn[1,64,1024])

#define BATCH 64
#define SEQ   512
#define IDIM  1024
#define HID   1024
#define G3    3072

#define NBLK  128        // persistent blocks
#define UPB   8          // hidden units per block
#define RSTR  1032       // smem row stride for weights AND h (fp16 units)

// Scratch (device globals; no runtime allocation).
__device__ float  g_xproj[(size_t)BATCH * SEQ * G3];    // exact fp32 x_proj
__device__ __half g_in_h[(size_t)BATCH * SEQ * IDIM];   // fp16 inputs
__device__ __half g_wih_h[(size_t)G3 * IDIM];           // fp16 W_ih
__device__ __half g_whh_h[(size_t)G3 * IDIM];           // fp16 W_hh
__device__ __half g_h[2][(size_t)BATCH * HID];          // fp16 h ping-pong
__device__ int      g_bar_grp[8][64];                   // arrive counters, 256B apart
__device__ int      g_bar_root;
__device__ unsigned g_bar_rel[8][64];                   // release words, 256B apart

// ---------------------------------------------------------------------------
// helpers
// ---------------------------------------------------------------------------
__device__ __forceinline__ uint32_t smem_u32(const void* p) {
    uint32_t a;
    asm("{ .reg .u64 t; cvta.to.shared.u64 t, %1; cvt.u32.u64 %0, t; }" : "=r"(a) : "l"(p));
    return a;
}
__device__ __forceinline__ void cpa16(uint32_t dst, const void* src) {
    asm volatile("cp.async.ca.shared.global [%0], [%1], 16;" :: "r"(dst), "l"(src));
}
__device__ __forceinline__ void cpa16_cg(uint32_t dst, const void* src) {
    asm volatile("cp.async.cg.shared.global [%0], [%1], 16;" :: "r"(dst), "l"(src));
}
__device__ __forceinline__ void cpa_commit() { asm volatile("cp.async.commit_group;"); }
__device__ __forceinline__ void cpa_wait0()  { asm volatile("cp.async.wait_group 0;"); }
__device__ __forceinline__ void cpa_wait1()  { asm volatile("cp.async.wait_group 1;"); }
__device__ __forceinline__ void cpa_wait2()  { asm volatile("cp.async.wait_group 2;"); }

// ldmatrix wrappers
__device__ __forceinline__ void ldsm_x4(uint32_t* r, uint32_t addr) {
    asm volatile("ldmatrix.sync.aligned.m8n8.x4.shared.b16 {%0,%1,%2,%3}, [%4];"
        : "=r"(r[0]), "=r"(r[1]), "=r"(r[2]), "=r"(r[3]) : "r"(addr));
}
__device__ __forceinline__ void ldsm_x2(uint32_t* r, uint32_t addr) {
    asm volatile("ldmatrix.sync.aligned.m8n8.x2.shared.b16 {%0,%1}, [%2];"
        : "=r"(r[0]), "=r"(r[1]) : "r"(addr));
}

// D += A(16x16,f16,row) * B(16x8,f16,col), fp32 accumulate
__device__ __forceinline__ void mma16(float* c, const uint32_t* a, uint32_t b0, uint32_t b1) {
    asm volatile(
        "mma.sync.aligned.m16n8k16.row.col.f32.f16.f16.f32 "
        "{%0,%1,%2,%3}, {%4,%5,%6,%7}, {%8,%9}, {%0,%1,%2,%3};"
        : "+f"(c[0]), "+f"(c[1]), "+f"(c[2]), "+f"(c[3])
        : "r"(a[0]), "r"(a[1]), "r"(a[2]), "r"(a[3]), "r"(b0), "r"(b1));
}
__device__ __forceinline__ float sigmoidf_(float x) { return 1.f / (1.f + __expf(-x)); }

// Lockstep producer/consumer handshake: BOTH warps bar.sync (count 64).
// Producer cannot run ahead — its next sync blocks until the consumer's.
__device__ __forceinline__ void bar_sync64(int id) {
    asm volatile("bar.sync %0, 64;" :: "r"(id) : "memory");
}

// Grid barrier: tree arrival (8x16) + 8-word release fan-out, gen = step index.
__device__ __forceinline__ void grid_barrier(int bid, unsigned t) {
    __syncthreads();
    if (threadIdx.x == 0) {
        __threadfence();
        bool released = false;
        int prev = atomicAdd(&g_bar_grp[bid >> 4][0], 1);
        if (prev == 15) {
            int rprev = atomicAdd(&g_bar_root, 1);
            if (rprev == 7) {
                #pragma unroll
                for (int i = 0; i < 8; i++)
                    asm volatile("st.relaxed.gpu.s32 [%0], %1;"
                                 :: "l"(&g_bar_grp[i][0]), "r"(0));
                asm volatile("st.relaxed.gpu.s32 [%0], %1;"
                             :: "l"(&g_bar_root), "r"(0));
                #pragma unroll
                for (int i = 0; i < 8; i++)
                    asm volatile("st.release.gpu.u32 [%0], %1;"
                                 :: "l"(&g_bar_rel[i][0]), "r"(t + 1));
                released = true;
            }
        }
        if (!released) {
            unsigned cur;
            const unsigned* rw = &g_bar_rel[bid >> 4][0];
            do {
                asm volatile("ld.acquire.gpu.u32 %0, [%1];" : "=r"(cur) : "l"(rw));
            } while (cur < t + 1);
        }
    }
    __syncthreads();
}

__global__ void init_bar_kernel() {
    if (threadIdx.x < 8) { g_bar_grp[threadIdx.x][0] = 0; g_bar_rel[threadIdx.x][0] = 0; }
    if (threadIdx.x == 0) g_bar_root = 0;
}

// ---------------------------------------------------------------------------
// fp32 -> fp16 conversion pre-pass
// ---------------------------------------------------------------------------
__global__ void half_kernel(const float4* __restrict__ src, uint2* __restrict__ dst, int n4)
{
    int i = blockIdx.x * 256 + threadIdx.x;
    if (i < n4) {
        float4 v = src[i];
        __half2 lo = __floats2half2_rn(v.x, v.y);
        __half2 hi = __floats2half2_rn(v.z, v.w);
        uint2 r;
        r.x = *(uint32_t*)&lo;
        r.y = *(uint32_t*)&hi;
        dst[i] = r;
    }
}

// ---------------------------------------------------------------------------
// x_proj GEMM (fp16 mma): C[32768,3072] = A @ W^T + bias (fp32 out)
// BM=128 BN=128 BK=32, 4-stage cp.async, 128 threads, 64x64 warp tiles.
// ---------------------------------------------------------------------------
#define XBK2   32
#define XPAD2  40
#define XROWS  256

__global__ __launch_bounds__(128, 2)
void xproj_h(const __half* __restrict__ A,
             const __half* __restrict__ W,
             const float* __restrict__ bias)
{
    extern __shared__ __half smh[];          // [4][256][40] fp16
    const uint32_t smb = smem_u32(smh);

    const int bm = blockIdx.y, bn = blockIdx.x;
    const int tid = threadIdx.x;
    const int w = tid >> 5, lane = tid & 31;
    const int g = lane >> 2, q = lane & 3;
    const int wm = (w & 1) * 64;
    const int wn = (w >> 1) * 64;

    const __half* Abase = A + (size_t)bm * 128 * IDIM;
    const __half* Wbase = W + (size_t)bn * 128 * IDIM;

    float acc[4][8][4];
    #pragma unroll
    for (int i = 0; i < 4; i++)
        #pragma unroll
        for (int j = 0; j < 8; j++)
            #pragma unroll
            for (int k = 0; k < 4; k++) acc[i][j][k] = 0.f;

    auto load_stage = [&](int s) {
        int buf = s & 3;
        int k0 = s * XBK2;
        #pragma unroll
        for (int i = 0; i < 8; i++) {
            int idx = tid + i * 128;
            int row = idx >> 2;
            int c   = idx & 3;
            const __half* src = (row < 128)
                ? (Abase + (size_t)row * IDIM + k0 + c * 8)
                : (Wbase + (size_t)(row - 128) * IDIM + k0 + c * 8);
            cpa16(smb + (((buf * XROWS + row) * XPAD2 + c * 8) << 1), src);
        }
    };

    load_stage(0); cpa_commit();
    load_stage(1); cpa_commit();
    load_stage(2); cpa_commit();
    cpa_wait2();
    __syncthreads();

    for (int kc = 0; kc < 32; kc++) {
        if (kc + 3 < 32) { load_stage(kc + 3); cpa_commit(); }

        const __half* S = smh + (size_t)(kc & 3) * XROWS * XPAD2;
        #pragma unroll
        for (int ks = 0; ks < 2; ks++) {
            const int kof = ks * 16;
            uint32_t a[4][4];
            #pragma unroll
            for (int mt = 0; mt < 4; mt++) {
                int r = wm + mt * 16;
                a[mt][0] = *(const uint32_t*)&S[(r + g) * XPAD2 + kof + 2 * q];
                a[mt][1] = *(const uint32_t*)&S[(r + g + 8) * XPAD2 + kof + 2 * q];
                a[mt][2] = *(const uint32_t*)&S[(r + g) * XPAD2 + kof + 2 * q + 8];
                a[mt][3] = *(const uint32_t*)&S[(r + g + 8) * XPAD2 + kof + 2 * q + 8];
            }
            uint32_t b0[8], b1[8];
            #pragma unroll
            for (int nt = 0; nt < 8; nt++) {
                int c = 128 + wn + nt * 8 + g;
                b0[nt] = *(const uint32_t*)&S[c * XPAD2 + kof + 2 * q];
                b1[nt] = *(const uint32_t*)&S[c * XPAD2 + kof + 2 * q + 8];
            }
            #pragma unroll
            for (int mt = 0; mt < 4; mt++)
                #pragma unroll
                for (int nt = 0; nt < 8; nt++)
                    mma16(acc[mt][nt], a[mt], b0[nt], b1[nt]);
        }

        if (kc + 1 < 32) {
            if (kc <= 28) cpa_wait2();
            else if (kc == 29) cpa_wait1();
            else cpa_wait0();
            __syncthreads();
        }
    }

    #pragma unroll
    for (int mt = 0; mt < 4; mt++) {
        #pragma unroll
        for (int nt = 0; nt < 8; nt++) {
            int row = bm * 128 + wm + mt * 16 + g;
            int col = bn * 128 + wn + nt * 8 + 2 * q;
            float b0 = bias[col], b1 = bias[col + 1];
            *(float2*)(g_xproj + (size_t)row * G3 + col) =
                make_float2(acc[mt][nt][0] + b0, acc[mt][nt][1] + b1);
            *(float2*)(g_xproj + (size_t)(row + 8) * G3 + col) =
                make_float2(acc[mt][nt][2] + b0, acc[mt][nt][3] + b1);
        }
    }
}

// ---------------------------------------------------------------------------
// Persistent GRU recurrence v7: 128 blocks x 256 threads, warp-specialized,
// LOCKSTEP handshake (both producer and consumer bar.sync — deadlock-free).
// Warps 0-3: GEMM + gating for batches w*16..w*16+15.
// Warps 4-7: h loaders for partner warp (w-4), 8 cp.async commit groups.
// ---------------------------------------------------------------------------
__global__ __launch_bounds__(256, 1)
void gru_persistent_h7(const __half* __restrict__ Whh_h,
                       const float* __restrict__ bhh,
                       const float* __restrict__ h0,
                       float* __restrict__ out)
{
    extern __shared__ __half smh[];
    __half* Ws = smh;                     // [24][RSTR]
    __half* Hs = smh + 24 * RSTR;         // [64][RSTR] full h
    const uint32_t wsb = smem_u32(Ws);
    const uint32_t hsb = smem_u32(Hs);

    const int tid = threadIdx.x;
    const int w = tid >> 5, lane = tid & 31;
    const int g = lane >> 2, q = lane & 3;
    const int j0 = blockIdx.x * UPB;
    const int jc = j0 + 2 * q;
    const int bid = blockIdx.x;

    // ---- resident weights: 24 rows x 1024 fp16 (3072 cpa16, all 256 thr) ----
    for (int i = tid; i < 24 * 128; i += 256) {
        int r = i >> 7, cq = i & 127;
        int gate = r >> 3, u = r & 7;
        cpa16(wsb + ((r * RSTR + cq * 8) << 1),
              Whh_h + (size_t)(gate * HID + j0 + u) * HID + cq * 8);
    }
    cpa_commit();
    cpa_wait0();
    __syncthreads();

    __half* ghb = &g_h[0][0];

    if (w >= 4) {
        // ================= LOADER WARP (partner p = w-4) =================
        const int p = w - 4;
        const int wrow = p * 16;
        const int barid = 1 + p;
        const int lrow = lane >> 3;       // 0..3
        const int lcq  = lane & 7;        // 0..7

        for (int t = 0; t < SEQ; t++) {
            const __half* hread = ghb + (size_t)(t & 1) * BATCH * HID;

            // issue all 8 groups (2 chunks of 64 cols each)
            #pragma unroll
            for (int g8 = 0; g8 < 8; g8++) {
                #pragma unroll
                for (int kh = 0; kh < 2; kh++) {
                    int kc = g8 * 2 + kh;
                    #pragma unroll
                    for (int ps = 0; ps < 4; ps++) {
                        int row = wrow + ps * 4 + lrow;
                        cpa16_cg(hsb + ((row * RSTR + kc * 64 + lcq * 8) << 1),
                                 hread + (size_t)row * HID + kc * 64 + lcq * 8);
                    }
                }
                cpa_commit();
            }
            // lockstep publication: wait data, then bar.sync with consumer
            #pragma unroll
            for (int g8 = 0; g8 < 8; g8++) {
                switch (g8) {
                    case 0: asm volatile("cp.async.wait_group 7;"); break;
                    case 1: asm volatile("cp.async.wait_group 6;"); break;
                    case 2: asm volatile("cp.async.wait_group 5;"); break;
                    case 3: asm volatile("cp.async.wait_group 4;"); break;
                    case 4: asm volatile("cp.async.wait_group 3;"); break;
                    case 5: asm volatile("cp.async.wait_group 2;"); break;
                    case 6: asm volatile("cp.async.wait_group 1;"); break;
                    case 7: asm volatile("cp.async.wait_group 0;"); break;
                }
                bar_sync64(barid);
            }
            if (t == SEQ - 1) break;
            grid_barrier(bid, (unsigned)t);
        }
        return;
    }

    // ==================== GEMM WARP (w = 0..3) ====================
    const int wrow = w * 16;
    const int barid = 1 + w;
    const int brow[2] = { wrow + g, wrow + g + 8 };

    // ldmatrix per-thread base addresses
    const int lrA = (lane & 7) + ((lane >> 3) & 1) * 8;
    const int lcA = ((lane >> 4) & 1) * 8;
    const uint32_t a_base  = hsb + (((wrow + lrA) * RSTR + lcA) << 1);
    const int ubB  = ((lane >> 4) & 1) * 8 + (lane & 7);
    const int kaB  = ((lane >> 3) & 1) * 8;
    const uint32_t b01_base = wsb + ((ubB * RSTR + kaB) << 1);
    const uint32_t b2_base  = wsb + (((16 + (lane & 7)) * RSTR + kaB) << 1);

    // per-thread persistent state
    float2 hp2[2];
    #pragma unroll
    for (int rh = 0; rh < 2; rh++)
        hp2[rh] = *(const float2*)(h0 + (size_t)brow[rh] * HID + jc);
    float2 bh2[3];
    #pragma unroll
    for (int gate = 0; gate < 3; gate++)
        bh2[gate] = *(const float2*)(bhh + gate * HID + jc);

    // prefetch xg for step 0
    float2 xg[2][3];
    #pragma unroll
    for (int rh = 0; rh < 2; rh++)
        #pragma unroll
        for (int gate = 0; gate < 3; gate++)
            xg[rh][gate] = *(const float2*)(g_xproj +
                ((size_t)brow[rh] * SEQ + 0) * G3 + gate * HID + jc);

    for (int t = 0; t < SEQ; t++) {
        __half* hwrite = ghb + (size_t)((t + 1) & 1) * BATCH * HID;

        float acc[3][4];
        #pragma unroll
        for (int i = 0; i < 3; i++)
            #pragma unroll
            for (int k = 0; k < 4; k++) acc[i][k] = 0.f;

        // consume 8 groups as the loader publishes them (lockstep bar.sync)
        #pragma unroll
        for (int g8 = 0; g8 < 8; g8++) {
            bar_sync64(barid);
            #pragma unroll
            for (int kh = 0; kh < 2; kh++) {
                int kc = g8 * 2 + kh;
                #pragma unroll
                for (int ks = 0; ks < 4; ks++) {
                    const uint32_t kb = (uint32_t)(kc * 64 + ks * 16) << 1;
                    uint32_t a[4], b01[4], b2[2];
                    ldsm_x4(a, a_base + kb);
                    ldsm_x4(b01, b01_base + kb);
                    ldsm_x2(b2, b2_base + kb);
                    mma16(acc[0], a, b01[0], b01[1]);
                    mma16(acc[1], a, b01[2], b01[3]);
                    mma16(acc[2], a, b2[0], b2[1]);
                }
            }
        }

        // epilogue: gates + state update
        #pragma unroll
        for (int rh = 0; rh < 2; rh++) {
            float hx[2];
            #pragma unroll
            for (int e = 0; e < 2; e++) {
                float xr = e ? xg[rh][0].y : xg[rh][0].x;
                float xz = e ? xg[rh][1].y : xg[rh][1].x;
                float xn = e ? xg[rh][2].y : xg[rh][2].x;
                float br = e ? bh2[0].y : bh2[0].x;
                float bz = e ? bh2[1].y : bh2[1].x;
                float bn = e ? bh2[2].y : bh2[2].x;
                float hp = e ? hp2[rh].y : hp2[rh].x;
                float rr = sigmoidf_(xr + acc[0][rh * 2 + e] + br);
                float zz = sigmoidf_(xz + acc[1][rh * 2 + e] + bz);
                float nn = tanhf(xn + rr * (acc[2][rh * 2 + e] + bn));
                hx[e] = (1.f - zz) * nn + zz * hp;
            }
            hp2[rh] = make_float2(hx[0], hx[1]);
            *(float2*)(out + ((size_t)brow[rh] * SEQ + t) * HID + jc) =
                make_float2(hx[0], hx[1]);
            __half2 hh = __floats2half2_rn(hx[0], hx[1]);
            *(__half2*)(hwrite + (size_t)brow[rh] * HID + jc) = hh;
        }
        if (t == SEQ - 1) {
            #pragma unroll
            for (int rh = 0; rh < 2; rh++)
                *(float2*)(out + (size_t)BATCH * SEQ * HID +
                           (size_t)brow[rh] * HID + jc) = hp2[rh];
            break;
        }

        // prefetch xg for t+1 (latency hides under the barrier)
        #pragma unroll
        for (int rh = 0; rh < 2; rh++)
            #pragma unroll
            for (int gate = 0; gate < 3; gate++)
                xg[rh][gate] = *(const float2*)(g_xproj +
                    ((size_t)brow[rh] * SEQ + (t + 1)) * G3 + gate * HID + jc);

        grid_barrier(bid, (unsigned)t);
    }
}

// ---------------------------------------------------------------------------
extern "C" void kernel_launch(void* const* d_in, const int* in_sizes, int n_in,
                              void* d_out, int out_size)
{
    const float* inputs = (const float*)d_in[0];
    const float* h0     = (const float*)d_in[1];
    const float* wih    = (const float*)d_in[2];
    const float* whh    = (const float*)d_in[3];
    const float* bih    = (const float*)d_in[4];
    const float* bhh    = (const float*)d_in[5];
    float* out = (float*)d_out;

    const int XP_SMEM = 4 * XROWS * XPAD2 * 2;                 // 81920
    const int GP_SMEM = (24 * RSTR + 64 * RSTR) * 2;           // 181632
    static bool attr_done = false;
    if (!attr_done) {
        cudaFuncSetAttribute(xproj_h, cudaFuncAttributeMaxDynamicSharedMemorySize, XP_SMEM);
        cudaFuncSetAttribute(gru_persistent_h7, cudaFuncAttributeMaxDynamicSharedMemorySize, GP_SMEM);
        attr_done = true;
    }

    __half* in_h;  cudaGetSymbolAddress((void**)&in_h,  g_in_h);
    __half* wih_h; cudaGetSymbolAddress((void**)&wih_h, g_wih_h);
    __half* whh_h; cudaGetSymbolAddress((void**)&whh_h, g_whh_h);
    __half* hbuf;  cudaGetSymbolAddress((void**)&hbuf,  g_h);

    // Phase -1: reset barrier state (required on every graph replay).
    init_bar_kernel<<<1, 32>>>();

    // Phase 0: fp16-convert mma operands.
    int n4 = BATCH * SEQ * IDIM / 4;
    half_kernel<<<(n4 + 255) / 256, 256>>>((const float4*)inputs, (uint2*)in_h, n4);
    n4 = G3 * IDIM / 4;
    half_kernel<<<(n4 + 255) / 256, 256>>>((const float4*)wih, (uint2*)wih_h, n4);
    half_kernel<<<(n4 + 255) / 256, 256>>>((const float4*)whh, (uint2*)whh_h, n4);
    n4 = BATCH * HID / 4;
    half_kernel<<<(n4 + 255) / 256, 256>>>((const float4*)h0, (uint2*)hbuf, n4);

    // Phase 1: x_proj (fp16 mma)
    dim3 grid_x(G3 / 128, (BATCH * SEQ) / 128);   // (24, 256)
    xproj_h<<<grid_x, 128, XP_SMEM>>>(in_h, wih_h, bih);

    // Phase 2: persistent recurrence (warp-specialized, lockstep handshake)
    gru_persistent_h7<<<NBLK, 256, GP_SMEM>>>(whh_h, bhh, h0, out);
}

// round 16
// speedup vs baseline: 1.0067x; 1.0067x over previous
#include <cuda_runtime.h>
#include <cuda_fp16.h>
#include <math.h>
#include <stdint.h>

// GRU: inputs[64,512,1024], h0[1,64,1024], weight_ih[3072,1024], weight_hh[3072,1024],
//      bias_ih[3072], bias_hh[3072]
// out = concat(outputs[64,512,1024], hn[1,64,1024])

#define BATCH 64
#define SEQ   512
#define IDIM  1024
#define HID   1024
#define G3    3072

#define NBLK  128        // persistent blocks
#define UPB   8          // hidden units per block
#define RSTR  1032       // smem row stride for weights AND h (fp16 units)

// Scratch (device globals; no runtime allocation).
__device__ float  g_xproj[(size_t)BATCH * SEQ * G3];    // exact fp32 x_proj
__device__ __half g_in_h[(size_t)BATCH * SEQ * IDIM];   // fp16 inputs
__device__ __half g_wih_h[(size_t)G3 * IDIM];           // fp16 W_ih
__device__ __half g_whh_h[(size_t)G3 * IDIM];           // fp16 W_hh
__device__ __half g_h[2][(size_t)BATCH * HID];          // fp16 h ping-pong
__device__ int      g_bar_grp[8][64];                   // arrive counters, 256B apart
__device__ int      g_bar_root;
__device__ unsigned g_bar_rel[8][64];                   // release words, 256B apart

// ---------------------------------------------------------------------------
// helpers
// ---------------------------------------------------------------------------
__device__ __forceinline__ uint32_t smem_u32(const void* p) {
    uint32_t a;
    asm("{ .reg .u64 t; cvta.to.shared.u64 t, %1; cvt.u32.u64 %0, t; }" : "=r"(a) : "l"(p));
    return a;
}
__device__ __forceinline__ void cpa16(uint32_t dst, const void* src) {
    asm volatile("cp.async.ca.shared.global [%0], [%1], 16;" :: "r"(dst), "l"(src));
}
__device__ __forceinline__ void cpa16_cg(uint32_t dst, const void* src) {
    asm volatile("cp.async.cg.shared.global [%0], [%1], 16;" :: "r"(dst), "l"(src));
}
__device__ __forceinline__ void cpa_commit() { asm volatile("cp.async.commit_group;"); }
__device__ __forceinline__ void cpa_wait0()  { asm volatile("cp.async.wait_group 0;"); }
__device__ __forceinline__ void cpa_wait1()  { asm volatile("cp.async.wait_group 1;"); }
__device__ __forceinline__ void cpa_wait2()  { asm volatile("cp.async.wait_group 2;"); }

// ldmatrix wrappers
__device__ __forceinline__ void ldsm_x4(uint32_t* r, uint32_t addr) {
    asm volatile("ldmatrix.sync.aligned.m8n8.x4.shared.b16 {%0,%1,%2,%3}, [%4];"
        : "=r"(r[0]), "=r"(r[1]), "=r"(r[2]), "=r"(r[3]) : "r"(addr));
}
__device__ __forceinline__ void ldsm_x2(uint32_t* r, uint32_t addr) {
    asm volatile("ldmatrix.sync.aligned.m8n8.x2.shared.b16 {%0,%1}, [%2];"
        : "=r"(r[0]), "=r"(r[1]) : "r"(addr));
}

// D += A(16x16,f16,row) * B(16x8,f16,col), fp32 accumulate
__device__ __forceinline__ void mma16(float* c, const uint32_t* a, uint32_t b0, uint32_t b1) {
    asm volatile(
        "mma.sync.aligned.m16n8k16.row.col.f32.f16.f16.f32 "
        "{%0,%1,%2,%3}, {%4,%5,%6,%7}, {%8,%9}, {%0,%1,%2,%3};"
        : "+f"(c[0]), "+f"(c[1]), "+f"(c[2]), "+f"(c[3])
        : "r"(a[0]), "r"(a[1]), "r"(a[2]), "r"(a[3]), "r"(b0), "r"(b1));
}
__device__ __forceinline__ float sigmoidf_(float x) { return 1.f / (1.f + __expf(-x)); }

// Grid barrier: tree arrival (8x16), generation = step index (no gen load on
// the arrival path), 8-word release fan-out (16 pollers/word instead of 128).
__device__ __forceinline__ void grid_barrier(int bid, unsigned t) {
    __syncthreads();
    if (threadIdx.x == 0) {
        __threadfence();
        bool released = false;
        int prev = atomicAdd(&g_bar_grp[bid >> 4][0], 1);
        if (prev == 15) {
            int rprev = atomicAdd(&g_bar_root, 1);
            if (rprev == 7) {
                #pragma unroll
                for (int i = 0; i < 8; i++)
                    asm volatile("st.relaxed.gpu.s32 [%0], %1;"
                                 :: "l"(&g_bar_grp[i][0]), "r"(0));
                asm volatile("st.relaxed.gpu.s32 [%0], %1;"
                             :: "l"(&g_bar_root), "r"(0));
                #pragma unroll
                for (int i = 0; i < 8; i++)
                    asm volatile("st.release.gpu.u32 [%0], %1;"
                                 :: "l"(&g_bar_rel[i][0]), "r"(t + 1));
                released = true;
            }
        }
        if (!released) {
            unsigned cur;
            const unsigned* rw = &g_bar_rel[bid >> 4][0];
            do {
                __nanosleep(32);
                asm volatile("ld.acquire.gpu.u32 %0, [%1];" : "=r"(cur) : "l"(rw));
            } while (cur < t + 1);
        }
    }
    __syncthreads();
}

__global__ void init_bar_kernel() {
    if (threadIdx.x < 8) { g_bar_grp[threadIdx.x][0] = 0; g_bar_rel[threadIdx.x][0] = 0; }
    if (threadIdx.x == 0) g_bar_root = 0;
}

// ---------------------------------------------------------------------------
// fp32 -> fp16 conversion pre-pass
// ---------------------------------------------------------------------------
__global__ void half_kernel(const float4* __restrict__ src, uint2* __restrict__ dst, int n4)
{
    int i = blockIdx.x * 256 + threadIdx.x;
    if (i < n4) {
        float4 v = src[i];
        __half2 lo = __floats2half2_rn(v.x, v.y);
        __half2 hi = __floats2half2_rn(v.z, v.w);
        uint2 r;
        r.x = *(uint32_t*)&lo;
        r.y = *(uint32_t*)&hi;
        dst[i] = r;
    }
}

// ---------------------------------------------------------------------------
// x_proj GEMM (fp16 mma): C[32768,3072] = A @ W^T + bias (fp32 out)
// BM=128 BN=128 BK=32, 4-stage cp.async, 128 threads, 64x64 warp tiles.
// ---------------------------------------------------------------------------
#define XBK2   32
#define XPAD2  40
#define XROWS  256

__global__ __launch_bounds__(128, 2)
void xproj_h(const __half* __restrict__ A,
             const __half* __restrict__ W,
             const float* __restrict__ bias)
{
    extern __shared__ __half smh[];          // [4][256][40] fp16
    const uint32_t smb = smem_u32(smh);

    const int bm = blockIdx.y, bn = blockIdx.x;
    const int tid = threadIdx.x;
    const int w = tid >> 5, lane = tid & 31;
    const int g = lane >> 2, q = lane & 3;
    const int wm = (w & 1) * 64;
    const int wn = (w >> 1) * 64;

    const __half* Abase = A + (size_t)bm * 128 * IDIM;
    const __half* Wbase = W + (size_t)bn * 128 * IDIM;

    float acc[4][8][4];
    #pragma unroll
    for (int i = 0; i < 4; i++)
        #pragma unroll
        for (int j = 0; j < 8; j++)
            #pragma unroll
            for (int k = 0; k < 4; k++) acc[i][j][k] = 0.f;

    auto load_stage = [&](int s) {
        int buf = s & 3;
        int k0 = s * XBK2;
        #pragma unroll
        for (int i = 0; i < 8; i++) {
            int idx = tid + i * 128;
            int row = idx >> 2;
            int c   = idx & 3;
            const __half* src = (row < 128)
                ? (Abase + (size_t)row * IDIM + k0 + c * 8)
                : (Wbase + (size_t)(row - 128) * IDIM + k0 + c * 8);
            cpa16(smb + (((buf * XROWS + row) * XPAD2 + c * 8) << 1), src);
        }
    };

    load_stage(0); cpa_commit();
    load_stage(1); cpa_commit();
    load_stage(2); cpa_commit();
    cpa_wait2();
    __syncthreads();

    for (int kc = 0; kc < 32; kc++) {
        if (kc + 3 < 32) { load_stage(kc + 3); cpa_commit(); }

        const __half* S = smh + (size_t)(kc & 3) * XROWS * XPAD2;
        #pragma unroll
        for (int ks = 0; ks < 2; ks++) {
            const int kof = ks * 16;
            uint32_t a[4][4];
            #pragma unroll
            for (int mt = 0; mt < 4; mt++) {
                int r = wm + mt * 16;
                a[mt][0] = *(const uint32_t*)&S[(r + g) * XPAD2 + kof + 2 * q];
                a[mt][1] = *(const uint32_t*)&S[(r + g + 8) * XPAD2 + kof + 2 * q];
                a[mt][2] = *(const uint32_t*)&S[(r + g) * XPAD2 + kof + 2 * q + 8];
                a[mt][3] = *(const uint32_t*)&S[(r + g + 8) * XPAD2 + kof + 2 * q + 8];
            }
            uint32_t b0[8], b1[8];
            #pragma unroll
            for (int nt = 0; nt < 8; nt++) {
                int c = 128 + wn + nt * 8 + g;
                b0[nt] = *(const uint32_t*)&S[c * XPAD2 + kof + 2 * q];
                b1[nt] = *(const uint32_t*)&S[c * XPAD2 + kof + 2 * q + 8];
            }
            #pragma unroll
            for (int mt = 0; mt < 4; mt++)
                #pragma unroll
                for (int nt = 0; nt < 8; nt++)
                    mma16(acc[mt][nt], a[mt], b0[nt], b1[nt]);
        }

        if (kc + 1 < 32) {
            if (kc <= 28) cpa_wait2();
            else if (kc == 29) cpa_wait1();
            else cpa_wait0();
            __syncthreads();
        }
    }

    #pragma unroll
    for (int mt = 0; mt < 4; mt++) {
        #pragma unroll
        for (int nt = 0; nt < 8; nt++) {
            int row = bm * 128 + wm + mt * 16 + g;
            int col = bn * 128 + wn + nt * 8 + 2 * q;
            float b0 = bias[col], b1 = bias[col + 1];
            *(float2*)(g_xproj + (size_t)row * G3 + col) =
                make_float2(acc[mt][nt][0] + b0, acc[mt][nt][1] + b1);
            *(float2*)(g_xproj + (size_t)(row + 8) * G3 + col) =
                make_float2(acc[mt][nt][2] + b0, acc[mt][nt][3] + b1);
        }
    }
}

// ---------------------------------------------------------------------------
// Persistent GRU recurrence (R11 champion + barrier latency cuts):
// 128 blocks x 128 threads, warp-private h, ldmatrix fragments.
// ---------------------------------------------------------------------------
__global__ __launch_bounds__(128, 1)
void gru_persistent_h8(const __half* __restrict__ Whh_h,
                       const float* __restrict__ bhh,
                       const float* __restrict__ h0,
                       float* __restrict__ out)
{
    extern __shared__ __half smh[];
    __half* Ws = smh;                     // [24][RSTR]
    __half* Hs = smh + 24 * RSTR;         // [64][RSTR] full h
    const uint32_t wsb = smem_u32(Ws);
    const uint32_t hsb = smem_u32(Hs);

    const int tid = threadIdx.x;
    const int w = tid >> 5, lane = tid & 31;
    const int g = lane >> 2, q = lane & 3;
    const int j0 = blockIdx.x * UPB;
    const int jc = j0 + 2 * q;
    const int brow[2] = { w * 16 + g, w * 16 + g + 8 };
    const int wrow = w * 16;
    const int bid = blockIdx.x;

    // ldmatrix per-thread base addresses
    const int lrA = (lane & 7) + ((lane >> 3) & 1) * 8;
    const int lcA = ((lane >> 4) & 1) * 8;
    const uint32_t a_base  = hsb + (((wrow + lrA) * RSTR + lcA) << 1);
    const int ubB  = ((lane >> 4) & 1) * 8 + (lane & 7);
    const int kaB  = ((lane >> 3) & 1) * 8;
    const uint32_t b01_base = wsb + ((ubB * RSTR + kaB) << 1);
    const uint32_t b2_base  = wsb + (((16 + (lane & 7)) * RSTR + kaB) << 1);

    // ---- resident weights: 24 rows x 1024 fp16 (3072 cpa16) ----
    for (int i = tid; i < 24 * 128; i += 128) {
        int r = i >> 7, cq = i & 127;
        int gate = r >> 3, u = r & 7;
        cpa16(wsb + ((r * RSTR + cq * 8) << 1),
              Whh_h + (size_t)(gate * HID + j0 + u) * HID + cq * 8);
    }
    cpa_commit();
    cpa_wait0();
    __syncthreads();

    // ---- per-thread persistent state ----
    float2 hp2[2];
    #pragma unroll
    for (int rh = 0; rh < 2; rh++)
        hp2[rh] = *(const float2*)(h0 + (size_t)brow[rh] * HID + jc);
    float2 bh2[3];
    #pragma unroll
    for (int gate = 0; gate < 3; gate++)
        bh2[gate] = *(const float2*)(bhh + gate * HID + jc);

    __half* ghb = &g_h[0][0];
    const int lrow = lane >> 3;
    const int lcq  = lane & 7;

    // prefetch xg for step 0
    float2 xg[2][3];
    #pragma unroll
    for (int rh = 0; rh < 2; rh++)
        #pragma unroll
        for (int gate = 0; gate < 3; gate++)
            xg[rh][gate] = *(const float2*)(g_xproj +
                ((size_t)brow[rh] * SEQ + 0) * G3 + gate * HID + jc);

    for (int t = 0; t < SEQ; t++) {
        const __half* hread = ghb + (size_t)(t & 1) * BATCH * HID;
        __half* hwrite     = ghb + (size_t)((t + 1) & 1) * BATCH * HID;

        // ---- issue ALL h loads: warp-private rows, 8 commit groups ----
        #pragma unroll
        for (int g8 = 0; g8 < 8; g8++) {
            #pragma unroll
            for (int kh = 0; kh < 2; kh++) {
                int kc = g8 * 2 + kh;
                #pragma unroll
                for (int p = 0; p < 4; p++) {
                    int row = wrow + p * 4 + lrow;
                    cpa16_cg(hsb + ((row * RSTR + kc * 64 + lcq * 8) << 1),
                             hread + (size_t)row * HID + kc * 64 + lcq * 8);
                }
            }
            cpa_commit();
        }

        float acc[3][4];
        #pragma unroll
        for (int i = 0; i < 3; i++)
            #pragma unroll
            for (int k = 0; k < 4; k++) acc[i][k] = 0.f;

        // ---- consume: per-warp group waits, ldmatrix fragments ----
        #pragma unroll
        for (int g8 = 0; g8 < 8; g8++) {
            switch (g8) {
                case 0: asm volatile("cp.async.wait_group 7;"); break;
                case 1: asm volatile("cp.async.wait_group 6;"); break;
                case 2: asm volatile("cp.async.wait_group 5;"); break;
                case 3: asm volatile("cp.async.wait_group 4;"); break;
                case 4: asm volatile("cp.async.wait_group 3;"); break;
                case 5: asm volatile("cp.async.wait_group 2;"); break;
                case 6: asm volatile("cp.async.wait_group 1;"); break;
                case 7: asm volatile("cp.async.wait_group 0;"); break;
            }
            __syncwarp();
            #pragma unroll
            for (int kh = 0; kh < 2; kh++) {
                int kc = g8 * 2 + kh;
                #pragma unroll
                for (int ks = 0; ks < 4; ks++) {
                    const uint32_t kb = (uint32_t)(kc * 64 + ks * 16) << 1;
                    uint32_t a[4], b01[4], b2[2];
                    ldsm_x4(a, a_base + kb);
                    ldsm_x4(b01, b01_base + kb);
                    ldsm_x2(b2, b2_base + kb);
                    mma16(acc[0], a, b01[0], b01[1]);
                    mma16(acc[1], a, b01[2], b01[3]);
                    mma16(acc[2], a, b2[0], b2[1]);
                }
            }
        }

        // ---- epilogue: gates + state update ----
        #pragma unroll
        for (int rh = 0; rh < 2; rh++) {
            float hx[2];
            #pragma unroll
            for (int e = 0; e < 2; e++) {
                float xr = e ? xg[rh][0].y : xg[rh][0].x;
                float xz = e ? xg[rh][1].y : xg[rh][1].x;
                float xn = e ? xg[rh][2].y : xg[rh][2].x;
                float br = e ? bh2[0].y : bh2[0].x;
                float bz = e ? bh2[1].y : bh2[1].x;
                float bn = e ? bh2[2].y : bh2[2].x;
                float hp = e ? hp2[rh].y : hp2[rh].x;
                float rr = sigmoidf_(xr + acc[0][rh * 2 + e] + br);
                float zz = sigmoidf_(xz + acc[1][rh * 2 + e] + bz);
                float nn = tanhf(xn + rr * (acc[2][rh * 2 + e] + bn));
                hx[e] = (1.f - zz) * nn + zz * hp;
            }
            hp2[rh] = make_float2(hx[0], hx[1]);
            *(float2*)(out + ((size_t)brow[rh] * SEQ + t) * HID + jc) =
                make_float2(hx[0], hx[1]);
            __half2 hh = __floats2half2_rn(hx[0], hx[1]);
            *(__half2*)(hwrite + (size_t)brow[rh] * HID + jc) = hh;
        }
        if (t == SEQ - 1) {
            #pragma unroll
            for (int rh = 0; rh < 2; rh++)
                *(float2*)(out + (size_t)BATCH * SEQ * HID +
                           (size_t)brow[rh] * HID + jc) = hp2[rh];
            break;
        }

        // prefetch xg for t+1 (latency hides under the barrier)
        #pragma unroll
        for (int rh = 0; rh < 2; rh++)
            #pragma unroll
            for (int gate = 0; gate < 3; gate++)
                xg[rh][gate] = *(const float2*)(g_xproj +
                    ((size_t)brow[rh] * SEQ + (t + 1)) * G3 + gate * HID + jc);

        grid_barrier(bid, (unsigned)t);
    }
}

// ---------------------------------------------------------------------------
extern "C" void kernel_launch(void* const* d_in, const int* in_sizes, int n_in,
                              void* d_out, int out_size)
{
    const float* inputs = (const float*)d_in[0];
    const float* h0     = (const float*)d_in[1];
    const float* wih    = (const float*)d_in[2];
    const float* whh    = (const float*)d_in[3];
    const float* bih    = (const float*)d_in[4];
    const float* bhh    = (const float*)d_in[5];
    float* out = (float*)d_out;

    const int XP_SMEM = 4 * XROWS * XPAD2 * 2;                 // 81920
    const int GP_SMEM = (24 * RSTR + 64 * RSTR) * 2;           // 181632
    static bool attr_done = false;
    if (!attr_done) {
        cudaFuncSetAttribute(xproj_h, cudaFuncAttributeMaxDynamicSharedMemorySize, XP_SMEM);
        cudaFuncSetAttribute(gru_persistent_h8, cudaFuncAttributeMaxDynamicSharedMemorySize, GP_SMEM);
        attr_done = true;
    }

    __half* in_h;  cudaGetSymbolAddress((void**)&in_h,  g_in_h);
    __half* wih_h; cudaGetSymbolAddress((void**)&wih_h, g_wih_h);
    __half* whh_h; cudaGetSymbolAddress((void**)&whh_h, g_whh_h);
    __half* hbuf;  cudaGetSymbolAddress((void**)&hbuf,  g_h);

    // Phase -1: reset barrier state (required on every graph replay).
    init_bar_kernel<<<1, 32>>>();

    // Phase 0: fp16-convert mma operands.
    int n4 = BATCH * SEQ * IDIM / 4;
    half_kernel<<<(n4 + 255) / 256, 256>>>((const float4*)inputs, (uint2*)in_h, n4);
    n4 = G3 * IDIM / 4;
    half_kernel<<<(n4 + 255) / 256, 256>>>((const float4*)wih, (uint2*)wih_h, n4);
    half_kernel<<<(n4 + 255) / 256, 256>>>((const float4*)whh, (uint2*)whh_h, n4);
    n4 = BATCH * HID / 4;
    half_kernel<<<(n4 + 255) / 256, 256>>>((const float4*)h0, (uint2*)hbuf, n4);

    // Phase 1: x_proj (fp16 mma)
    dim3 grid_x(G3 / 128, (BATCH * SEQ) / 128);   // (24, 256)
    xproj_h<<<grid_x, 128, XP_SMEM>>>(in_h, wih_h, bih);

    // Phase 2: persistent recurrence
    gru_persistent_h8<<<NBLK, 128, GP_SMEM>>>(whh_h, bhh, h0, out);
}

// round 17
// speedup vs baseline: 1.1988x; 1.1908x over previous
#include <cuda_runtime.h>
#include <cuda_fp16.h>
#include <math.h>
#include <stdint.h>

// GRU: inputs[64,512,1024], h0[1,64,1024], weight_ih[3072,1024], weight_hh[3072,1024],
//      bias_ih[3072], bias_hh[3072]
// out = concat(outputs[64,512,1024], hn[1,64,1024])

#define BATCH 64
#define SEQ   512
#define IDIM  1024
#define HID   1024
#define G3    3072

#define NBLK  128        // persistent blocks
#define UPB   8          // hidden units per block
#define RSTR  1032       // smem row stride for weights AND h (fp16 units)

// Scratch (device globals; no runtime allocation).
__device__ float  g_xproj[(size_t)BATCH * SEQ * G3];    // exact fp32 x_proj
__device__ __half g_in_h[(size_t)BATCH * SEQ * IDIM];   // fp16 inputs
__device__ __half g_wih_h[(size_t)G3 * IDIM];           // fp16 W_ih
__device__ __half g_whh_h[(size_t)G3 * IDIM];           // fp16 W_hh
__device__ __half g_h[2][(size_t)BATCH * HID];          // fp16 h ping-pong
__device__ int      g_bar_grp[8][64];                   // group counters, 256B apart
__device__ int      g_bar_root;
__device__ unsigned g_bar_gen;                          // single release word

// ---------------------------------------------------------------------------
// helpers
// ---------------------------------------------------------------------------
__device__ __forceinline__ uint32_t smem_u32(const void* p) {
    uint32_t a;
    asm("{ .reg .u64 t; cvta.to.shared.u64 t, %1; cvt.u32.u64 %0, t; }" : "=r"(a) : "l"(p));
    return a;
}
__device__ __forceinline__ void cpa16(uint32_t dst, const void* src) {
    asm volatile("cp.async.ca.shared.global [%0], [%1], 16;" :: "r"(dst), "l"(src));
}
__device__ __forceinline__ void cpa16_cg(uint32_t dst, const void* src) {
    asm volatile("cp.async.cg.shared.global [%0], [%1], 16;" :: "r"(dst), "l"(src));
}
__device__ __forceinline__ void cpa_commit() { asm volatile("cp.async.commit_group;"); }
__device__ __forceinline__ void cpa_wait0()  { asm volatile("cp.async.wait_group 0;"); }
__device__ __forceinline__ void cpa_wait1()  { asm volatile("cp.async.wait_group 1;"); }
__device__ __forceinline__ void cpa_wait2()  { asm volatile("cp.async.wait_group 2;"); }

// ldmatrix wrappers
__device__ __forceinline__ void ldsm_x4(uint32_t* r, uint32_t addr) {
    asm volatile("ldmatrix.sync.aligned.m8n8.x4.shared.b16 {%0,%1,%2,%3}, [%4];"
        : "=r"(r[0]), "=r"(r[1]), "=r"(r[2]), "=r"(r[3]) : "r"(addr));
}
__device__ __forceinline__ void ldsm_x2(uint32_t* r, uint32_t addr) {
    asm volatile("ldmatrix.sync.aligned.m8n8.x2.shared.b16 {%0,%1}, [%2];"
        : "=r"(r[0]), "=r"(r[1]) : "r"(addr));
}

// D += A(16x16,f16,row) * B(16x8,f16,col), fp32 accumulate
__device__ __forceinline__ void mma16(float* c, const uint32_t* a, uint32_t b0, uint32_t b1) {
    asm volatile(
        "mma.sync.aligned.m16n8k16.row.col.f32.f16.f16.f32 "
        "{%0,%1,%2,%3}, {%4,%5,%6,%7}, {%8,%9}, {%0,%1,%2,%3};"
        : "+f"(c[0]), "+f"(c[1]), "+f"(c[2]), "+f"(c[3])
        : "r"(a[0]), "r"(a[1]), "r"(a[2]), "r"(a[3]), "r"(b0), "r"(b1));
}
__device__ __forceinline__ float sigmoidf_(float x) { return 1.f / (1.f + __expf(-x)); }

// Grid barrier: tree arrival (8x16), generation = step index (no gen LOAD on
// the arrival path), single release word, TIGHT poll (no nanosleep) — exactly
// R11 except the removed gen read.
__device__ __forceinline__ void grid_barrier(int bid, unsigned t) {
    __syncthreads();
    if (threadIdx.x == 0) {
        __threadfence();
        bool released = false;
        int prev = atomicAdd(&g_bar_grp[bid >> 4][0], 1);
        if (prev == 15) {
            int rprev = atomicAdd(&g_bar_root, 1);
            if (rprev == 7) {
                #pragma unroll
                for (int i = 0; i < 8; i++)
                    asm volatile("st.relaxed.gpu.s32 [%0], %1;"
                                 :: "l"(&g_bar_grp[i][0]), "r"(0));
                asm volatile("st.relaxed.gpu.s32 [%0], %1;"
                             :: "l"(&g_bar_root), "r"(0));
                asm volatile("st.release.gpu.u32 [%0], %1;"
                             :: "l"(&g_bar_gen), "r"(t + 1));
                released = true;
            }
        }
        if (!released) {
            unsigned cur;
            do {
                asm volatile("ld.acquire.gpu.u32 %0, [%1];" : "=r"(cur) : "l"(&g_bar_gen));
            } while (cur < t + 1);
        }
    }
    __syncthreads();
}

__global__ void init_bar_kernel() {
    if (threadIdx.x < 8) g_bar_grp[threadIdx.x][0] = 0;
    if (threadIdx.x == 0) { g_bar_root = 0; g_bar_gen = 0; }
}

// ---------------------------------------------------------------------------
// fp32 -> fp16 conversion pre-pass
// ---------------------------------------------------------------------------
__global__ void half_kernel(const float4* __restrict__ src, uint2* __restrict__ dst, int n4)
{
    int i = blockIdx.x * 256 + threadIdx.x;
    if (i < n4) {
        float4 v = src[i];
        __half2 lo = __floats2half2_rn(v.x, v.y);
        __half2 hi = __floats2half2_rn(v.z, v.w);
        uint2 r;
        r.x = *(uint32_t*)&lo;
        r.y = *(uint32_t*)&hi;
        dst[i] = r;
    }
}

// ---------------------------------------------------------------------------
// x_proj GEMM (fp16 mma): C[32768,3072] = A @ W^T + bias (fp32 out)
// BM=128 BN=128 BK=32, 4-stage cp.async, 128 threads, 64x64 warp tiles.
// ---------------------------------------------------------------------------
#define XBK2   32
#define XPAD2  40
#define XROWS  256

__global__ __launch_bounds__(128, 2)
void xproj_h(const __half* __restrict__ A,
             const __half* __restrict__ W,
             const float* __restrict__ bias)
{
    extern __shared__ __half smh[];          // [4][256][40] fp16
    const uint32_t smb = smem_u32(smh);

    const int bm = blockIdx.y, bn = blockIdx.x;
    const int tid = threadIdx.x;
    const int w = tid >> 5, lane = tid & 31;
    const int g = lane >> 2, q = lane & 3;
    const int wm = (w & 1) * 64;
    const int wn = (w >> 1) * 64;

    const __half* Abase = A + (size_t)bm * 128 * IDIM;
    const __half* Wbase = W + (size_t)bn * 128 * IDIM;

    float acc[4][8][4];
    #pragma unroll
    for (int i = 0; i < 4; i++)
        #pragma unroll
        for (int j = 0; j < 8; j++)
            #pragma unroll
            for (int k = 0; k < 4; k++) acc[i][j][k] = 0.f;

    auto load_stage = [&](int s) {
        int buf = s & 3;
        int k0 = s * XBK2;
        #pragma unroll
        for (int i = 0; i < 8; i++) {
            int idx = tid + i * 128;
            int row = idx >> 2;
            int c   = idx & 3;
            const __half* src = (row < 128)
                ? (Abase + (size_t)row * IDIM + k0 + c * 8)
                : (Wbase + (size_t)(row - 128) * IDIM + k0 + c * 8);
            cpa16(smb + (((buf * XROWS + row) * XPAD2 + c * 8) << 1), src);
        }
    };

    load_stage(0); cpa_commit();
    load_stage(1); cpa_commit();
    load_stage(2); cpa_commit();
    cpa_wait2();
    __syncthreads();

    for (int kc = 0; kc < 32; kc++) {
        if (kc + 3 < 32) { load_stage(kc + 3); cpa_commit(); }

        const __half* S = smh + (size_t)(kc & 3) * XROWS * XPAD2;
        #pragma unroll
        for (int ks = 0; ks < 2; ks++) {
            const int kof = ks * 16;
            uint32_t a[4][4];
            #pragma unroll
            for (int mt = 0; mt < 4; mt++) {
                int r = wm + mt * 16;
                a[mt][0] = *(const uint32_t*)&S[(r + g) * XPAD2 + kof + 2 * q];
                a[mt][1] = *(const uint32_t*)&S[(r + g + 8) * XPAD2 + kof + 2 * q];
                a[mt][2] = *(const uint32_t*)&S[(r + g) * XPAD2 + kof + 2 * q + 8];
                a[mt][3] = *(const uint32_t*)&S[(r + g + 8) * XPAD2 + kof + 2 * q + 8];
            }
            uint32_t b0[8], b1[8];
            #pragma unroll
            for (int nt = 0; nt < 8; nt++) {
                int c = 128 + wn + nt * 8 + g;
                b0[nt] = *(const uint32_t*)&S[c * XPAD2 + kof + 2 * q];
                b1[nt] = *(const uint32_t*)&S[c * XPAD2 + kof + 2 * q + 8];
            }
            #pragma unroll
            for (int mt = 0; mt < 4; mt++)
                #pragma unroll
                for (int nt = 0; nt < 8; nt++)
                    mma16(acc[mt][nt], a[mt], b0[nt], b1[nt]);
        }

        if (kc + 1 < 32) {
            if (kc <= 28) cpa_wait2();
            else if (kc == 29) cpa_wait1();
            else cpa_wait0();
            __syncthreads();
        }
    }

    #pragma unroll
    for (int mt = 0; mt < 4; mt++) {
        #pragma unroll
        for (int nt = 0; nt < 8; nt++) {
            int row = bm * 128 + wm + mt * 16 + g;
            int col = bn * 128 + wn + nt * 8 + 2 * q;
            float b0 = bias[col], b1 = bias[col + 1];
            *(float2*)(g_xproj + (size_t)row * G3 + col) =
                make_float2(acc[mt][nt][0] + b0, acc[mt][nt][1] + b1);
            *(float2*)(g_xproj + (size_t)(row + 8) * G3 + col) =
                make_float2(acc[mt][nt][2] + b0, acc[mt][nt][3] + b1);
        }
    }
}

// ---------------------------------------------------------------------------
// Persistent GRU recurrence (R11 champion, barrier arrival gen-load removed):
// 128 blocks x 128 threads, warp-private h, ldmatrix fragments.
// ---------------------------------------------------------------------------
__global__ __launch_bounds__(128, 1)
void gru_persistent_h9(const __half* __restrict__ Whh_h,
                       const float* __restrict__ bhh,
                       const float* __restrict__ h0,
                       float* __restrict__ out)
{
    extern __shared__ __half smh[];
    __half* Ws = smh;                     // [24][RSTR]
    __half* Hs = smh + 24 * RSTR;         // [64][RSTR] full h
    const uint32_t wsb = smem_u32(Ws);
    const uint32_t hsb = smem_u32(Hs);

    const int tid = threadIdx.x;
    const int w = tid >> 5, lane = tid & 31;
    const int g = lane >> 2, q = lane & 3;
    const int j0 = blockIdx.x * UPB;
    const int jc = j0 + 2 * q;
    const int brow[2] = { w * 16 + g, w * 16 + g + 8 };
    const int wrow = w * 16;
    const int bid = blockIdx.x;

    // ldmatrix per-thread base addresses
    const int lrA = (lane & 7) + ((lane >> 3) & 1) * 8;
    const int lcA = ((lane >> 4) & 1) * 8;
    const uint32_t a_base  = hsb + (((wrow + lrA) * RSTR + lcA) << 1);
    const int ubB  = ((lane >> 4) & 1) * 8 + (lane & 7);
    const int kaB  = ((lane >> 3) & 1) * 8;
    const uint32_t b01_base = wsb + ((ubB * RSTR + kaB) << 1);
    const uint32_t b2_base  = wsb + (((16 + (lane & 7)) * RSTR + kaB) << 1);

    // ---- resident weights: 24 rows x 1024 fp16 (3072 cpa16) ----
    for (int i = tid; i < 24 * 128; i += 128) {
        int r = i >> 7, cq = i & 127;
        int gate = r >> 3, u = r & 7;
        cpa16(wsb + ((r * RSTR + cq * 8) << 1),
              Whh_h + (size_t)(gate * HID + j0 + u) * HID + cq * 8);
    }
    cpa_commit();
    cpa_wait0();
    __syncthreads();

    // ---- per-thread persistent state ----
    float2 hp2[2];
    #pragma unroll
    for (int rh = 0; rh < 2; rh++)
        hp2[rh] = *(const float2*)(h0 + (size_t)brow[rh] * HID + jc);
    float2 bh2[3];
    #pragma unroll
    for (int gate = 0; gate < 3; gate++)
        bh2[gate] = *(const float2*)(bhh + gate * HID + jc);

    __half* ghb = &g_h[0][0];
    const int lrow = lane >> 3;
    const int lcq  = lane & 7;

    // prefetch xg for step 0
    float2 xg[2][3];
    #pragma unroll
    for (int rh = 0; rh < 2; rh++)
        #pragma unroll
        for (int gate = 0; gate < 3; gate++)
            xg[rh][gate] = *(const float2*)(g_xproj +
                ((size_t)brow[rh] * SEQ + 0) * G3 + gate * HID + jc);

    for (int t = 0; t < SEQ; t++) {
        const __half* hread = ghb + (size_t)(t & 1) * BATCH * HID;
        __half* hwrite     = ghb + (size_t)((t + 1) & 1) * BATCH * HID;

        // ---- issue ALL h loads: warp-private rows, 8 commit groups ----
        #pragma unroll
        for (int g8 = 0; g8 < 8; g8++) {
            #pragma unroll
            for (int kh = 0; kh < 2; kh++) {
                int kc = g8 * 2 + kh;
                #pragma unroll
                for (int p = 0; p < 4; p++) {
                    int row = wrow + p * 4 + lrow;
                    cpa16_cg(hsb + ((row * RSTR + kc * 64 + lcq * 8) << 1),
                             hread + (size_t)row * HID + kc * 64 + lcq * 8);
                }
            }
            cpa_commit();
        }

        float acc[3][4];
        #pragma unroll
        for (int i = 0; i < 3; i++)
            #pragma unroll
            for (int k = 0; k < 4; k++) acc[i][k] = 0.f;

        // ---- consume: per-warp group waits, ldmatrix fragments ----
        #pragma unroll
        for (int g8 = 0; g8 < 8; g8++) {
            switch (g8) {
                case 0: asm volatile("cp.async.wait_group 7;"); break;
                case 1: asm volatile("cp.async.wait_group 6;"); break;
                case 2: asm volatile("cp.async.wait_group 5;"); break;
                case 3: asm volatile("cp.async.wait_group 4;"); break;
                case 4: asm volatile("cp.async.wait_group 3;"); break;
                case 5: asm volatile("cp.async.wait_group 2;"); break;
                case 6: asm volatile("cp.async.wait_group 1;"); break;
                case 7: asm volatile("cp.async.wait_group 0;"); break;
            }
            __syncwarp();
            #pragma unroll
            for (int kh = 0; kh < 2; kh++) {
                int kc = g8 * 2 + kh;
                #pragma unroll
                for (int ks = 0; ks < 4; ks++) {
                    const uint32_t kb = (uint32_t)(kc * 64 + ks * 16) << 1;
                    uint32_t a[4], b01[4], b2[2];
                    ldsm_x4(a, a_base + kb);
                    ldsm_x4(b01, b01_base + kb);
                    ldsm_x2(b2, b2_base + kb);
                    mma16(acc[0], a, b01[0], b01[1]);
                    mma16(acc[1], a, b01[2], b01[3]);
                    mma16(acc[2], a, b2[0], b2[1]);
                }
            }
        }

        // ---- epilogue: gates + state update ----
        #pragma unroll
        for (int rh = 0; rh < 2; rh++) {
            float hx[2];
            #pragma unroll
            for (int e = 0; e < 2; e++) {
                float xr = e ? xg[rh][0].y : xg[rh][0].x;
                float xz = e ? xg[rh][1].y : xg[rh][1].x;
                float xn = e ? xg[rh][2].y : xg[rh][2].x;
                float br = e ? bh2[0].y : bh2[0].x;
                float bz = e ? bh2[1].y : bh2[1].x;
                float bn = e ? bh2[2].y : bh2[2].x;
                float hp = e ? hp2[rh].y : hp2[rh].x;
                float rr = sigmoidf_(xr + acc[0][rh * 2 + e] + br);
                float zz = sigmoidf_(xz + acc[1][rh * 2 + e] + bz);
                float nn = tanhf(xn + rr * (acc[2][rh * 2 + e] + bn));
                hx[e] = (1.f - zz) * nn + zz * hp;
            }
            hp2[rh] = make_float2(hx[0], hx[1]);
            *(float2*)(out + ((size_t)brow[rh] * SEQ + t) * HID + jc) =
                make_float2(hx[0], hx[1]);
            __half2 hh = __floats2half2_rn(hx[0], hx[1]);
            *(__half2*)(hwrite + (size_t)brow[rh] * HID + jc) = hh;
        }
        if (t == SEQ - 1) {
            #pragma unroll
            for (int rh = 0; rh < 2; rh++)
                *(float2*)(out + (size_t)BATCH * SEQ * HID +
                           (size_t)brow[rh] * HID + jc) = hp2[rh];
            break;
        }

        // prefetch xg for t+1 (latency hides under the barrier)
        #pragma unroll
        for (int rh = 0; rh < 2; rh++)
            #pragma unroll
            for (int gate = 0; gate < 3; gate++)
                xg[rh][gate] = *(const float2*)(g_xproj +
                    ((size_t)brow[rh] * SEQ + (t + 1)) * G3 + gate * HID + jc);

        grid_barrier(bid, (unsigned)t);
    }
}

// ---------------------------------------------------------------------------
extern "C" void kernel_launch(void* const* d_in, const int* in_sizes, int n_in,
                              void* d_out, int out_size)
{
    const float* inputs = (const float*)d_in[0];
    const float* h0     = (const float*)d_in[1];
    const float* wih    = (const float*)d_in[2];
    const float* whh    = (const float*)d_in[3];
    const float* bih    = (const float*)d_in[4];
    const float* bhh    = (const float*)d_in[5];
    float* out = (float*)d_out;

    const int XP_SMEM = 4 * XROWS * XPAD2 * 2;                 // 81920
    const int GP_SMEM = (24 * RSTR + 64 * RSTR) * 2;           // 181632
    static bool attr_done = false;
    if (!attr_done) {
        cudaFuncSetAttribute(xproj_h, cudaFuncAttributeMaxDynamicSharedMemorySize, XP_SMEM);
        cudaFuncSetAttribute(gru_persistent_h9, cudaFuncAttributeMaxDynamicSharedMemorySize, GP_SMEM);
        attr_done = true;
    }

    __half* in_h;  cudaGetSymbolAddress((void**)&in_h,  g_in_h);
    __half* wih_h; cudaGetSymbolAddress((void**)&wih_h, g_wih_h);
    __half* whh_h; cudaGetSymbolAddress((void**)&whh_h, g_whh_h);
    __half* hbuf;  cudaGetSymbolAddress((void**)&hbuf,  g_h);

    // Phase -1: reset barrier state (required on every graph replay).
    init_bar_kernel<<<1, 32>>>();

    // Phase 0: fp16-convert mma operands.
    int n4 = BATCH * SEQ * IDIM / 4;
    half_kernel<<<(n4 + 255) / 256, 256>>>((const float4*)inputs, (uint2*)in_h, n4);
    n4 = G3 * IDIM / 4;
    half_kernel<<<(n4 + 255) / 256, 256>>>((const float4*)wih, (uint2*)wih_h, n4);
    half_kernel<<<(n4 + 255) / 256, 256>>>((const float4*)whh, (uint2*)whh_h, n4);
    n4 = BATCH * HID / 4;
    half_kernel<<<(n4 + 255) / 256, 256>>>((const float4*)h0, (uint2*)hbuf, n4);

    // Phase 1: x_proj (fp16 mma)
    dim3 grid_x(G3 / 128, (BATCH * SEQ) / 128);   // (24, 256)
    xproj_h<<<grid_x, 128, XP_SMEM>>>(in_h, wih_h, bih);

    // Phase 2: persistent recurrence
    gru_persistent_h9<<<NBLK, 128, GP_SMEM>>>(whh_h, bhh, h0, out);
}